// round 7
// baseline (speedup 1.0000x reference)
#include <cuda_runtime.h>
#include <math.h>

// ---------------------------------------------------------------------------
// Problem constants
// ---------------------------------------------------------------------------
#define BATCH      512
#define SEQ        64
#define DIM        1024
#define NUM_ACT    8
#define ABINS      256
#define D_STATE    16
#define D_CONV     4
#define D_INNER    2048            // 2*DIM
#define DT_RANK    64              // ceil(1024/16)
#define XD         96              // DT_RANK + 2*D_STATE
#define ROWS       (BATCH * NUM_ACT)   // 4096 token rows
#define TABROWS    ((NUM_ACT - 1) * ABINS)  // 1792 distinct bin embeddings used

// ---------------------------------------------------------------------------
// Scratch (static device allocations; no cudaMalloc allowed)
// ---------------------------------------------------------------------------
__device__ float d_sos    [BATCH * DIM];          //  2 MB : mean of encoded_state
__device__ float d_tproj  [TABROWS * 2 * D_INNER];// 29 MB : bin_table @ in_proj^T
__device__ float d_sosproj[BATCH * 2 * D_INNER];  //  8 MB : sos @ in_proj^T
__device__ float d_xc     [ROWS * D_INNER];       // 33 MB : conv+silu output (u)
__device__ float d_xdbl   [ROWS * XD];            // 1.5MB : x_proj output (dt|B|C)
__device__ float d_delta  [ROWS * D_INNER];       // 33 MB : softplus(dt@W + b)
__device__ float d_y      [ROWS * D_INNER];       // 33 MB : scan output (gated)
__device__ float d_embed  [ROWS * DIM];           // 16 MB : out_proj output

// ---------------------------------------------------------------------------
// Generic NT SGEMM: C[m,n] = sum_k A[m,k]*B[n,k]
//   A: M x K (row-major, lda), B: N x K (row-major, ldb), C: M x N (ldc)
//   Requirements: M % 128 == 0, K % 16 == 0, lda/ldb % 4 == 0. N guarded.
//   EPI: 0 = none
//        1 = softplus(x + bias[n])
//        2 = sigmoid(x) stored at column (n+255)&255   (requires N == 256)
//   blockIdx.z batching via element strides sAz/sBz/sCz.
// ---------------------------------------------------------------------------
#define BM 128
#define BN 128
#define BK 16

template<int EPI>
__global__ __launch_bounds__(256)
void sgemm_nt(const float* __restrict__ Ag, const float* __restrict__ Bg,
              float* __restrict__ Cg, int M, int N, int K,
              int lda, int ldb, int ldc,
              long sAz, long sBz, long sCz,
              const float* __restrict__ bias)
{
    const float* A = Ag + (long)blockIdx.z * sAz;
    const float* B = Bg + (long)blockIdx.z * sBz;
    float*       C = Cg + (long)blockIdx.z * sCz;

    __shared__ float As[BK][BM + 4];
    __shared__ float Bs[BK][BN + 4];

    const int tid = threadIdx.x;              // 256 threads
    const int bm  = blockIdx.y * BM;
    const int bn  = blockIdx.x * BN;

    const int lr = tid >> 2;                  // 0..63 (load row)
    const int lc = (tid & 3) * 4;             // 0,4,8,12 (load col, float4)

    const int tm = (tid >> 4) * 8;            // 0..120 (compute m offset)
    const int tn = (tid & 15) * 8;            // 0..120 (compute n offset)

    float acc[8][8];
    #pragma unroll
    for (int i = 0; i < 8; i++)
        #pragma unroll
        for (int j = 0; j < 8; j++) acc[i][j] = 0.f;

    for (int k0 = 0; k0 < K; k0 += BK) {
        // --- stage A tile (128 x 16), transposed into As[k][m] ---
        #pragma unroll
        for (int r = 0; r < 2; r++) {
            int row = lr + r * 64;
            float4 v = *reinterpret_cast<const float4*>(
                A + (long)(bm + row) * lda + k0 + lc);
            As[lc + 0][row] = v.x; As[lc + 1][row] = v.y;
            As[lc + 2][row] = v.z; As[lc + 3][row] = v.w;
        }
        // --- stage B tile (128 x 16) with N guard ---
        #pragma unroll
        for (int r = 0; r < 2; r++) {
            int row = lr + r * 64;
            float4 v = make_float4(0.f, 0.f, 0.f, 0.f);
            if (bn + row < N)
                v = *reinterpret_cast<const float4*>(
                    B + (long)(bn + row) * ldb + k0 + lc);
            Bs[lc + 0][row] = v.x; Bs[lc + 1][row] = v.y;
            Bs[lc + 2][row] = v.z; Bs[lc + 3][row] = v.w;
        }
        __syncthreads();

        #pragma unroll
        for (int k = 0; k < BK; k++) {
            float af[8], bf[8];
            #pragma unroll
            for (int i = 0; i < 8; i++) af[i] = As[k][tm + i];
            #pragma unroll
            for (int j = 0; j < 8; j++) bf[j] = Bs[k][tn + j];
            #pragma unroll
            for (int i = 0; i < 8; i++)
                #pragma unroll
                for (int j = 0; j < 8; j++)
                    acc[i][j] = fmaf(af[i], bf[j], acc[i][j]);
        }
        __syncthreads();
    }

    // --- epilogue ---
    #pragma unroll
    for (int i = 0; i < 8; i++) {
        int m = bm + tm + i;
        #pragma unroll
        for (int j = 0; j < 8; j++) {
            int n = bn + tn + j;
            if (n < N) {
                float v = acc[i][j];
                if (EPI == 1) {                 // bias + softplus (stable)
                    v += bias[n];
                    v = fmaxf(v, 0.f) + log1pf(expf(-fabsf(v)));
                }
                int nout = n;
                if (EPI == 2) {                 // sigmoid + roll(-1) on bins
                    nout = (n + 255) & 255;
                    v = 1.f / (1.f + __expf(-v));
                }
                C[(long)m * ldc + nout] = v;
            }
        }
    }
}

// ---------------------------------------------------------------------------
// sos = mean over seq axis of encoded_state  [b, 64, 1024] -> [b, 1024]
// ---------------------------------------------------------------------------
__global__ void mean_kernel(const float* __restrict__ es, float* __restrict__ sos)
{
    int b = blockIdx.x;
    for (int d = threadIdx.x; d < DIM; d += blockDim.x) {
        const float* p = es + (long)b * SEQ * DIM + d;
        float s = 0.f;
        #pragma unroll
        for (int t = 0; t < SEQ; t++) s += p[(long)t * DIM];
        sos[b * DIM + d] = s * (1.f / SEQ);
    }
}

// Row of the (virtual) xz matrix for (batch b, token t):
//   t == 0 -> sosproj[b], else tproj[(t-1)*256 + actions[b, t-1]]
__device__ __forceinline__ const float* xz_row(int b, int t,
                                               const int* __restrict__ actions,
                                               const float* __restrict__ sosproj,
                                               const float* __restrict__ tproj)
{
    if (t == 0) return sosproj + (long)b * (2 * D_INNER);
    int act = actions[b * (NUM_ACT - 1) + (t - 1)];
    return tproj + (long)((t - 1) * ABINS + act) * (2 * D_INNER);
}

// ---------------------------------------------------------------------------
// Causal depthwise conv (D_CONV=4) + SiLU.  One block per token row (b,l).
// Reads xh = xz[:, :D_INNER] through the gather indirection.
// ---------------------------------------------------------------------------
__global__ void conv_silu_kernel(const int* __restrict__ actions,
                                 const float* __restrict__ sosproj,
                                 const float* __restrict__ tproj,
                                 const float* __restrict__ conv_w,  // [2048,4]
                                 const float* __restrict__ conv_b,  // [2048]
                                 float* __restrict__ xc)            // [4096,2048]
{
    int row = blockIdx.x;            // 0..4095 = b*8 + l
    int b = row >> 3, l = row & 7;
    const float* p[4];
    #pragma unroll
    for (int k = 0; k < 4; k++) {
        int t = l + k - 3;
        p[k] = (t >= 0) ? xz_row(b, t, actions, sosproj, tproj) : nullptr;
    }
    for (int c = threadIdx.x; c < D_INNER; c += blockDim.x) {
        float a = conv_b[c];
        #pragma unroll
        for (int k = 0; k < 4; k++)
            if (p[k]) a = fmaf(p[k][c], conv_w[c * 4 + k], a);
        xc[(long)row * D_INNER + c] = a / (1.f + __expf(-a));   // silu
    }
}

// ---------------------------------------------------------------------------
// Selective scan + skip (u*D) + SiLU(z) gating. One block per batch b.
// Thread handles 8 d-channels sequentially (d = tid + j*256).
// B/C (shared across d) staged in shared memory.
// ---------------------------------------------------------------------------
__global__ void scan_kernel(const float* __restrict__ xc,     // u  [4096,2048]
                            const float* __restrict__ delta,  //    [4096,2048]
                            const float* __restrict__ xdbl,   //    [4096,96]
                            const int*   __restrict__ actions,
                            const float* __restrict__ sosproj,
                            const float* __restrict__ tproj,
                            const float* __restrict__ A_log,  // [2048,16]
                            const float* __restrict__ Dp,     // [2048]
                            float* __restrict__ y)            //    [4096,2048]
{
    int b = blockIdx.x;
    int tid = threadIdx.x;           // 256

    __shared__ float Bs[NUM_ACT][D_STATE];
    __shared__ float Cs[NUM_ACT][D_STATE];
    if (tid < NUM_ACT * D_STATE) {
        int l = tid / D_STATE, n = tid % D_STATE;
        const float* r = xdbl + (long)(b * NUM_ACT + l) * XD;
        Bs[l][n] = r[DT_RANK + n];
        Cs[l][n] = r[DT_RANK + D_STATE + n];
    }
    __syncthreads();

    const float* zp[NUM_ACT];
    #pragma unroll
    for (int l = 0; l < NUM_ACT; l++)
        zp[l] = xz_row(b, l, actions, sosproj, tproj) + D_INNER;   // z half

    for (int j = 0; j < D_INNER / 256; j++) {
        int d = tid + j * 256;
        float Arow[D_STATE];
        #pragma unroll
        for (int n = 0; n < D_STATE; n++)
            Arow[n] = -__expf(A_log[d * D_STATE + n]);
        float Dd = Dp[d];
        float h[D_STATE];
        #pragma unroll
        for (int n = 0; n < D_STATE; n++) h[n] = 0.f;

        #pragma unroll
        for (int l = 0; l < NUM_ACT; l++) {
            long row = (long)(b * NUM_ACT + l);
            float dl = delta[row * D_INNER + d];
            float u  = xc[row * D_INNER + d];
            float du = dl * u;
            float yv = 0.f;
            #pragma unroll
            for (int n = 0; n < D_STATE; n++) {
                float dA = __expf(dl * Arow[n]);
                h[n] = fmaf(dA, h[n], du * Bs[l][n]);
                yv   = fmaf(h[n], Cs[l][n], yv);
            }
            yv = fmaf(u, Dd, yv);
            float z = zp[l][d];
            float sz = z / (1.f + __expf(-z));      // silu(z)
            y[row * D_INNER + d] = yv * sz;
        }
    }
}

// ---------------------------------------------------------------------------
// Launch
// ---------------------------------------------------------------------------
extern "C" void kernel_launch(void* const* d_in, const int* in_sizes, int n_in,
                              void* d_out, int out_size)
{
    const float* encoded_state = (const float*)d_in[0];   // [512,64,1024]
    const int*   actions       = (const int*)  d_in[1];   // [512,7]
    const float* tab           = (const float*)d_in[2];   // [8,256,1024]
    /* d_in[3] = gamma (unused by reference) */
    const float* in_proj_w     = (const float*)d_in[4];   // [4096,1024]
    const float* conv_w        = (const float*)d_in[5];   // [2048,4]
    const float* conv_b        = (const float*)d_in[6];   // [2048]
    const float* x_proj_w      = (const float*)d_in[7];   // [96,2048]
    const float* dt_proj_w     = (const float*)d_in[8];   // [2048,64]
    const float* dt_proj_b     = (const float*)d_in[9];   // [2048]
    const float* A_log         = (const float*)d_in[10];  // [2048,16]
    const float* D_param       = (const float*)d_in[11];  // [2048]
    const float* out_proj_w    = (const float*)d_in[12];  // [1024,2048]
    float* out = (float*)d_out;                           // [512,8,256]

    float *g_sos, *g_tproj, *g_sosproj, *g_xc, *g_xdbl, *g_delta, *g_y, *g_embed;
    cudaGetSymbolAddress((void**)&g_sos,     d_sos);
    cudaGetSymbolAddress((void**)&g_tproj,   d_tproj);
    cudaGetSymbolAddress((void**)&g_sosproj, d_sosproj);
    cudaGetSymbolAddress((void**)&g_xc,      d_xc);
    cudaGetSymbolAddress((void**)&g_xdbl,    d_xdbl);
    cudaGetSymbolAddress((void**)&g_delta,   d_delta);
    cudaGetSymbolAddress((void**)&g_y,       d_y);
    cudaGetSymbolAddress((void**)&g_embed,   d_embed);

    // 1) sos = mean(encoded_state, axis=seq)
    mean_kernel<<<BATCH, 256>>>(encoded_state, g_sos);

    // 2) tproj = bin_table[0:7*256] @ in_proj_w^T   (1792 x 4096, K=1024)
    sgemm_nt<0><<<dim3(2 * D_INNER / BN, TABROWS / BM, 1), 256>>>(
        tab, in_proj_w, g_tproj, TABROWS, 2 * D_INNER, DIM,
        DIM, DIM, 2 * D_INNER, 0, 0, 0, nullptr);

    // 3) sosproj = sos @ in_proj_w^T   (512 x 4096, K=1024)
    sgemm_nt<0><<<dim3(2 * D_INNER / BN, BATCH / BM, 1), 256>>>(
        g_sos, in_proj_w, g_sosproj, BATCH, 2 * D_INNER, DIM,
        DIM, DIM, 2 * D_INNER, 0, 0, 0, nullptr);

    // 4) xc = silu(causal_conv(xh)), xh gathered from {sosproj, tproj}
    conv_silu_kernel<<<ROWS, 256>>>(actions, g_sosproj, g_tproj,
                                    conv_w, conv_b, g_xc);

    // 5) x_dbl = xc @ x_proj_w^T   (4096 x 96, K=2048)
    sgemm_nt<0><<<dim3(1, ROWS / BM, 1), 256>>>(
        g_xc, x_proj_w, g_xdbl, ROWS, XD, D_INNER,
        D_INNER, D_INNER, XD, 0, 0, 0, nullptr);

    // 6) delta = softplus(dt @ dt_proj_w^T + dt_proj_b)  (4096 x 2048, K=64)
    sgemm_nt<1><<<dim3(D_INNER / BN, ROWS / BM, 1), 256>>>(
        g_xdbl, dt_proj_w, g_delta, ROWS, D_INNER, DT_RANK,
        XD, DT_RANK, D_INNER, 0, 0, 0, dt_proj_b);

    // 7) selective scan + u*D + silu(z) gating
    scan_kernel<<<BATCH, 256>>>(g_xc, g_delta, g_xdbl, actions,
                                g_sosproj, g_tproj, A_log, D_param, g_y);

    // 8) embed = y @ out_proj_w^T   (4096 x 1024, K=2048)
    sgemm_nt<0><<<dim3(DIM / BN, ROWS / BM, 1), 256>>>(
        g_y, out_proj_w, g_embed, ROWS, DIM, D_INNER,
        D_INNER, D_INNER, DIM, 0, 0, 0, nullptr);

    // 9) out[b,n,a] = sigmoid( embed[b,n,:] . tab[n,(a+1)%256,:] )
    //    batched over n via blockIdx.z; roll folded into store index.
    sgemm_nt<2><<<dim3(ABINS / BN, BATCH / BM, NUM_ACT), 256>>>(
        g_embed, tab, out, BATCH, ABINS, DIM,
        NUM_ACT * DIM, DIM, NUM_ACT * ABINS,
        DIM,                 /* A z-stride: embed + n*1024, lda = 8192 */
        (long)ABINS * DIM,   /* B z-stride: tab + n*256*1024 */
        ABINS,               /* C z-stride: out + n*256, ldc = 2048 */
        nullptr);
}

// round 8
// speedup vs baseline: 1.9511x; 1.9511x over previous
#include <cuda_runtime.h>
#include <math.h>
#include <stdint.h>

// ---------------------------------------------------------------------------
// Problem constants
// ---------------------------------------------------------------------------
#define BATCH      512
#define SEQ        64
#define DIM        1024
#define NUM_ACT    8
#define ABINS      256
#define D_STATE    16
#define D_CONV     4
#define D_INNER    2048            // 2*DIM
#define DT_RANK    64              // ceil(1024/16)
#define XD         96              // DT_RANK + 2*D_STATE
#define ROWS       (BATCH * NUM_ACT)        // 4096 token rows
#define TABROWS    ((NUM_ACT - 1) * ABINS)  // 1792 distinct bin embeddings used

// ---------------------------------------------------------------------------
// Scratch (static device allocations; no cudaMalloc allowed)
// ---------------------------------------------------------------------------
__device__ float d_sos    [BATCH * DIM];
__device__ float d_tproj  [TABROWS * 2 * D_INNER];
__device__ float d_sosproj[BATCH * 2 * D_INNER];
__device__ float d_xc     [ROWS * D_INNER];
__device__ float d_xdbl   [ROWS * XD];
__device__ float d_delta  [ROWS * D_INNER];
__device__ float d_y      [ROWS * D_INNER];
__device__ float d_embed  [ROWS * DIM];

// ---------------------------------------------------------------------------
// TF32 tensor-core NT GEMM: C[m,n] = sum_k A[m,k]*B[n,k]
//   Block tile 128x128xBK16, 8 warps, warp tile 64x32 (m16n8k8 MMAs).
//   Requirements: M % 128 == 0, K % 16 == 0, lda/ldb % 4 == 0. N guarded.
//   EPI: 0 = none
//        1 = softplus(x + bias[n])
//        2 = sigmoid(x) stored at column (n+255)&255   (requires N == 256)
//   blockIdx.z batching via element strides sAz/sBz/sCz.
// ---------------------------------------------------------------------------
#define BM  128
#define BN  128
#define BK  16
#define BKP 20   // smem pitch (floats): (20*g + c) mod 32 covers all banks

__device__ __forceinline__ float tf32r(float x) {
    unsigned u;
    asm("cvt.rna.tf32.f32 %0, %1;" : "=r"(u) : "f"(x));
    return __uint_as_float(u);
}

__device__ __forceinline__ void mma_tf32(float c[4],
                                         const unsigned a[4],
                                         const unsigned b[2]) {
    asm volatile(
        "mma.sync.aligned.m16n8k8.row.col.f32.tf32.tf32.f32 "
        "{%0,%1,%2,%3}, {%4,%5,%6,%7}, {%8,%9}, {%0,%1,%2,%3};\n"
        : "+f"(c[0]), "+f"(c[1]), "+f"(c[2]), "+f"(c[3])
        : "r"(a[0]), "r"(a[1]), "r"(a[2]), "r"(a[3]),
          "r"(b[0]), "r"(b[1]));
}

template<int EPI>
__global__ __launch_bounds__(256)
void gemm_tf32(const float* __restrict__ Ag, const float* __restrict__ Bg,
               float* __restrict__ Cg, int M, int N, int K,
               int lda, int ldb, int ldc,
               long sAz, long sBz, long sCz,
               const float* __restrict__ bias)
{
    const float* A = Ag + (long)blockIdx.z * sAz;
    const float* B = Bg + (long)blockIdx.z * sBz;
    float*       C = Cg + (long)blockIdx.z * sCz;

    __shared__ float As[2][BM][BKP];
    __shared__ float Bs[2][BN][BKP];

    const int tid  = threadIdx.x;
    const int warp = tid >> 5;
    const int lane = tid & 31;
    const int wm   = (warp >> 2) * 64;    // 0 or 64
    const int wn   = (warp & 3)  * 32;    // 0,32,64,96
    const int gid  = lane >> 2;           // 0..7
    const int tig  = lane & 3;            // 0..3

    const int bm = blockIdx.y * BM;
    const int bn = blockIdx.x * BN;

    const int lr = tid >> 2;              // 0..63 (stage row)
    const int lc = (tid & 3) * 4;         // 0,4,8,12 (stage k, float4)

    float acc[4][4][4];
    #pragma unroll
    for (int i = 0; i < 4; i++)
        #pragma unroll
        for (int j = 0; j < 4; j++)
            #pragma unroll
            for (int e = 0; e < 4; e++) acc[i][j][e] = 0.f;

    float4 av0, av1, bv0, bv1;

    auto load_g = [&](int k0) {
        av0 = *reinterpret_cast<const float4*>(A + (long)(bm + lr)      * lda + k0 + lc);
        av1 = *reinterpret_cast<const float4*>(A + (long)(bm + lr + 64) * lda + k0 + lc);
        bv0 = make_float4(0.f, 0.f, 0.f, 0.f);
        bv1 = make_float4(0.f, 0.f, 0.f, 0.f);
        if (bn + lr < N)
            bv0 = *reinterpret_cast<const float4*>(B + (long)(bn + lr)      * ldb + k0 + lc);
        if (bn + lr + 64 < N)
            bv1 = *reinterpret_cast<const float4*>(B + (long)(bn + lr + 64) * ldb + k0 + lc);
    };

    auto store_s = [&](int buf) {
        float4 t;
        t.x = tf32r(av0.x); t.y = tf32r(av0.y); t.z = tf32r(av0.z); t.w = tf32r(av0.w);
        *reinterpret_cast<float4*>(&As[buf][lr][lc]) = t;
        t.x = tf32r(av1.x); t.y = tf32r(av1.y); t.z = tf32r(av1.z); t.w = tf32r(av1.w);
        *reinterpret_cast<float4*>(&As[buf][lr + 64][lc]) = t;
        t.x = tf32r(bv0.x); t.y = tf32r(bv0.y); t.z = tf32r(bv0.z); t.w = tf32r(bv0.w);
        *reinterpret_cast<float4*>(&Bs[buf][lr][lc]) = t;
        t.x = tf32r(bv1.x); t.y = tf32r(bv1.y); t.z = tf32r(bv1.z); t.w = tf32r(bv1.w);
        *reinterpret_cast<float4*>(&Bs[buf][lr + 64][lc]) = t;
    };

    const int nk = K / BK;
    load_g(0);
    store_s(0);
    __syncthreads();

    for (int it = 0; it < nk; ++it) {
        if (it + 1 < nk) load_g((it + 1) * BK);
        const int buf = it & 1;

        #pragma unroll
        for (int kk = 0; kk < BK; kk += 8) {
            unsigned a[4][4], b[4][2];
            #pragma unroll
            for (int mt = 0; mt < 4; mt++) {
                int m = wm + mt * 16 + gid;
                a[mt][0] = __float_as_uint(As[buf][m    ][kk + tig]);
                a[mt][1] = __float_as_uint(As[buf][m + 8][kk + tig]);
                a[mt][2] = __float_as_uint(As[buf][m    ][kk + tig + 4]);
                a[mt][3] = __float_as_uint(As[buf][m + 8][kk + tig + 4]);
            }
            #pragma unroll
            for (int nt = 0; nt < 4; nt++) {
                int n = wn + nt * 8 + gid;
                b[nt][0] = __float_as_uint(Bs[buf][n][kk + tig]);
                b[nt][1] = __float_as_uint(Bs[buf][n][kk + tig + 4]);
            }
            #pragma unroll
            for (int mt = 0; mt < 4; mt++)
                #pragma unroll
                for (int nt = 0; nt < 4; nt++)
                    mma_tf32(acc[mt][nt], a[mt], b[nt]);
        }

        if (it + 1 < nk) store_s((it + 1) & 1);
        __syncthreads();
    }

    // --- epilogue ---
    #pragma unroll
    for (int mt = 0; mt < 4; mt++) {
        int m0 = bm + wm + mt * 16 + gid;
        #pragma unroll
        for (int nt = 0; nt < 4; nt++) {
            int col0 = bn + wn + nt * 8 + tig * 2;
            #pragma unroll
            for (int e = 0; e < 4; e++) {
                int m = m0 + ((e >> 1) ? 8 : 0);
                int n = col0 + (e & 1);
                if (n < N) {
                    float v = acc[mt][nt][e];
                    if (EPI == 1) {                 // bias + softplus (stable)
                        v += bias[n];
                        v = fmaxf(v, 0.f) + log1pf(expf(-fabsf(v)));
                    }
                    int nout = n;
                    if (EPI == 2) {                 // sigmoid + roll(-1) on bins
                        nout = (n + 255) & 255;
                        v = 1.f / (1.f + __expf(-v));
                    }
                    C[(long)m * ldc + nout] = v;
                }
            }
        }
    }
}

// ---------------------------------------------------------------------------
// sos = mean over seq axis of encoded_state  [b, 64, 1024] -> [b, 1024]
// ---------------------------------------------------------------------------
__global__ void mean_kernel(const float* __restrict__ es, float* __restrict__ sos)
{
    int b = blockIdx.x;
    for (int d = threadIdx.x; d < DIM; d += blockDim.x) {
        const float* p = es + (long)b * SEQ * DIM + d;
        float s = 0.f;
        #pragma unroll
        for (int t = 0; t < SEQ; t++) s += p[(long)t * DIM];
        sos[b * DIM + d] = s * (1.f / SEQ);
    }
}

// Row of the (virtual) xz matrix for (batch b, token t)
__device__ __forceinline__ const float* xz_row(int b, int t,
                                               const int* __restrict__ actions,
                                               const float* __restrict__ sosproj,
                                               const float* __restrict__ tproj)
{
    if (t == 0) return sosproj + (long)b * (2 * D_INNER);
    int act = actions[b * (NUM_ACT - 1) + (t - 1)];
    return tproj + (long)((t - 1) * ABINS + act) * (2 * D_INNER);
}

// ---------------------------------------------------------------------------
// Causal depthwise conv (D_CONV=4) + SiLU. One block per token row (b,l).
// ---------------------------------------------------------------------------
__global__ void conv_silu_kernel(const int* __restrict__ actions,
                                 const float* __restrict__ sosproj,
                                 const float* __restrict__ tproj,
                                 const float* __restrict__ conv_w,
                                 const float* __restrict__ conv_b,
                                 float* __restrict__ xc)
{
    int row = blockIdx.x;
    int b = row >> 3, l = row & 7;
    const float* p[4];
    #pragma unroll
    for (int k = 0; k < 4; k++) {
        int t = l + k - 3;
        p[k] = (t >= 0) ? xz_row(b, t, actions, sosproj, tproj) : nullptr;
    }
    for (int c = threadIdx.x; c < D_INNER; c += blockDim.x) {
        float a = conv_b[c];
        #pragma unroll
        for (int k = 0; k < 4; k++)
            if (p[k]) a = fmaf(p[k][c], conv_w[c * 4 + k], a);
        xc[(long)row * D_INNER + c] = a / (1.f + __expf(-a));
    }
}

// ---------------------------------------------------------------------------
// Selective scan + skip (u*D) + SiLU(z) gating. One block per batch b.
// ---------------------------------------------------------------------------
__global__ void scan_kernel(const float* __restrict__ xc,
                            const float* __restrict__ delta,
                            const float* __restrict__ xdbl,
                            const int*   __restrict__ actions,
                            const float* __restrict__ sosproj,
                            const float* __restrict__ tproj,
                            const float* __restrict__ A_log,
                            const float* __restrict__ Dp,
                            float* __restrict__ y)
{
    int b = blockIdx.x;
    int tid = threadIdx.x;

    __shared__ float Bs[NUM_ACT][D_STATE];
    __shared__ float Cs[NUM_ACT][D_STATE];
    if (tid < NUM_ACT * D_STATE) {
        int l = tid / D_STATE, n = tid % D_STATE;
        const float* r = xdbl + (long)(b * NUM_ACT + l) * XD;
        Bs[l][n] = r[DT_RANK + n];
        Cs[l][n] = r[DT_RANK + D_STATE + n];
    }
    __syncthreads();

    const float* zp[NUM_ACT];
    #pragma unroll
    for (int l = 0; l < NUM_ACT; l++)
        zp[l] = xz_row(b, l, actions, sosproj, tproj) + D_INNER;

    for (int j = 0; j < D_INNER / 256; j++) {
        int d = tid + j * 256;
        float Arow[D_STATE];
        #pragma unroll
        for (int n = 0; n < D_STATE; n++)
            Arow[n] = -__expf(A_log[d * D_STATE + n]);
        float Dd = Dp[d];
        float h[D_STATE];
        #pragma unroll
        for (int n = 0; n < D_STATE; n++) h[n] = 0.f;

        #pragma unroll
        for (int l = 0; l < NUM_ACT; l++) {
            long row = (long)(b * NUM_ACT + l);
            float dl = delta[row * D_INNER + d];
            float u  = xc[row * D_INNER + d];
            float du = dl * u;
            float yv = 0.f;
            #pragma unroll
            for (int n = 0; n < D_STATE; n++) {
                float dA = __expf(dl * Arow[n]);
                h[n] = fmaf(dA, h[n], du * Bs[l][n]);
                yv   = fmaf(h[n], Cs[l][n], yv);
            }
            yv = fmaf(u, Dd, yv);
            float z = zp[l][d];
            float sz = z / (1.f + __expf(-z));
            y[row * D_INNER + d] = yv * sz;
        }
    }
}

// ---------------------------------------------------------------------------
// Launch
// ---------------------------------------------------------------------------
extern "C" void kernel_launch(void* const* d_in, const int* in_sizes, int n_in,
                              void* d_out, int out_size)
{
    const float* encoded_state = (const float*)d_in[0];
    const int*   actions       = (const int*)  d_in[1];
    const float* tab           = (const float*)d_in[2];   // [8,256,1024]
    /* d_in[3] = gamma (unused by reference) */
    const float* in_proj_w     = (const float*)d_in[4];   // [4096,1024]
    const float* conv_w        = (const float*)d_in[5];
    const float* conv_b        = (const float*)d_in[6];
    const float* x_proj_w      = (const float*)d_in[7];   // [96,2048]
    const float* dt_proj_w     = (const float*)d_in[8];   // [2048,64]
    const float* dt_proj_b     = (const float*)d_in[9];
    const float* A_log         = (const float*)d_in[10];
    const float* D_param       = (const float*)d_in[11];
    const float* out_proj_w    = (const float*)d_in[12];  // [1024,2048]
    float* out = (float*)d_out;                           // [512,8,256]

    float *g_sos, *g_tproj, *g_sosproj, *g_xc, *g_xdbl, *g_delta, *g_y, *g_embed;
    cudaGetSymbolAddress((void**)&g_sos,     d_sos);
    cudaGetSymbolAddress((void**)&g_tproj,   d_tproj);
    cudaGetSymbolAddress((void**)&g_sosproj, d_sosproj);
    cudaGetSymbolAddress((void**)&g_xc,      d_xc);
    cudaGetSymbolAddress((void**)&g_xdbl,    d_xdbl);
    cudaGetSymbolAddress((void**)&g_delta,   d_delta);
    cudaGetSymbolAddress((void**)&g_y,       d_y);
    cudaGetSymbolAddress((void**)&g_embed,   d_embed);

    // 1) sos = mean(encoded_state, axis=seq)
    mean_kernel<<<BATCH, 256>>>(encoded_state, g_sos);

    // 2) tproj = bin_table[0:7*256] @ in_proj_w^T   (1792 x 4096, K=1024)
    gemm_tf32<0><<<dim3(2 * D_INNER / BN, TABROWS / BM, 1), 256>>>(
        tab, in_proj_w, g_tproj, TABROWS, 2 * D_INNER, DIM,
        DIM, DIM, 2 * D_INNER, 0, 0, 0, nullptr);

    // 3) sosproj = sos @ in_proj_w^T   (512 x 4096, K=1024)
    gemm_tf32<0><<<dim3(2 * D_INNER / BN, BATCH / BM, 1), 256>>>(
        g_sos, in_proj_w, g_sosproj, BATCH, 2 * D_INNER, DIM,
        DIM, DIM, 2 * D_INNER, 0, 0, 0, nullptr);

    // 4) xc = silu(causal_conv(xh)), xh gathered from {sosproj, tproj}
    conv_silu_kernel<<<ROWS, 256>>>(actions, g_sosproj, g_tproj,
                                    conv_w, conv_b, g_xc);

    // 5) x_dbl = xc @ x_proj_w^T   (4096 x 96, K=2048)
    gemm_tf32<0><<<dim3(1, ROWS / BM, 1), 256>>>(
        g_xc, x_proj_w, g_xdbl, ROWS, XD, D_INNER,
        D_INNER, D_INNER, XD, 0, 0, 0, nullptr);

    // 6) delta = softplus(dt @ dt_proj_w^T + dt_proj_b)  (4096 x 2048, K=64)
    gemm_tf32<1><<<dim3(D_INNER / BN, ROWS / BM, 1), 256>>>(
        g_xdbl, dt_proj_w, g_delta, ROWS, D_INNER, DT_RANK,
        XD, DT_RANK, D_INNER, 0, 0, 0, dt_proj_b);

    // 7) selective scan + u*D + silu(z) gating
    scan_kernel<<<BATCH, 256>>>(g_xc, g_delta, g_xdbl, actions,
                                g_sosproj, g_tproj, A_log, D_param, g_y);

    // 8) embed = y @ out_proj_w^T   (4096 x 1024, K=2048)
    gemm_tf32<0><<<dim3(DIM / BN, ROWS / BM, 1), 256>>>(
        g_y, out_proj_w, g_embed, ROWS, DIM, D_INNER,
        D_INNER, D_INNER, DIM, 0, 0, 0, nullptr);

    // 9) out[b,n,a] = sigmoid( embed[b,n,:] . tab[n,(a+1)%256,:] )
    gemm_tf32<2><<<dim3(ABINS / BN, BATCH / BM, NUM_ACT), 256>>>(
        g_embed, tab, out, BATCH, ABINS, DIM,
        NUM_ACT * DIM, DIM, NUM_ACT * ABINS,
        DIM, (long)ABINS * DIM, ABINS,
        nullptr);
}